// round 16
// baseline (speedup 1.0000x reference)
#include <cuda_runtime.h>
#include <cuda_fp16.h>
#include <math.h>
#include <cstdint>

// ---------------- problem constants ----------------
#define PPB   2256
#define MROWS 36096
#define NDET  48
#define NB    92
#define NLAB  133

// ---------------- scratch ----------------
__device__ __half g_deth[768 * 2048];
__device__ __half g_UVh[768 * 2048];                  // U'(=U+b1) | V
__device__ __half g_h2h[(size_t)MROWS * 1024];
__device__ float  g_sp[(size_t)MROWS * 512];
__device__ __half g_reh[(size_t)MROWS * 512];
__device__ __half g_W1t[2048 * 2048];
__device__ __half g_W2t[1024 * 1024];
__device__ __half g_W3t[512 * 1024];
__device__ __half g_R2t[512 * 256];
__device__ __half g_cwp[128 * 512];
__device__ double g_acc[3];
__device__ unsigned int g_cnt[2];

// ---------------- helpers ----------------
__device__ __forceinline__ uint32_t smem_to_u32(const void* p) {
    uint32_t a;
    asm("{ .reg .u64 t; cvta.to.shared.u64 t, %1; cvt.u32.u64 %0, t; }" : "=r"(a) : "l"(p));
    return a;
}
__device__ __forceinline__ uint32_t f2h2(float lo, float hi) {
    __half2 h = __floats2half2_rn(lo, hi);
    return *reinterpret_cast<uint32_t*>(&h);
}
__device__ __forceinline__ uint32_t hadd_relu2(uint32_t a, uint32_t b) {
    __half2 r = __hmax2(__hadd2(*reinterpret_cast<__half2*>(&a),
                                *reinterpret_cast<__half2*>(&b)),
                        __half2(__float2half_rn(0.f), __float2half_rn(0.f)));
    return *reinterpret_cast<uint32_t*>(&r);
}
__device__ __forceinline__ void mma16816(float* d,
                                         uint32_t a0, uint32_t a1, uint32_t a2, uint32_t a3,
                                         uint32_t b0, uint32_t b1) {
    asm volatile(
        "mma.sync.aligned.m16n8k16.row.col.f32.f16.f16.f32 "
        "{%0,%1,%2,%3}, {%4,%5,%6,%7}, {%8,%9}, {%0,%1,%2,%3};"
        : "+f"(d[0]), "+f"(d[1]), "+f"(d[2]), "+f"(d[3])
        : "r"(a0), "r"(a1), "r"(a2), "r"(a3), "r"(b0), "r"(b1));
}
__device__ __forceinline__ void ldsm_x4(uint32_t* r, uint32_t saddr) {
    asm volatile("ldmatrix.sync.aligned.m8n8.x4.shared.b16 {%0,%1,%2,%3}, [%4];"
                 : "=r"(r[0]), "=r"(r[1]), "=r"(r[2]), "=r"(r[3]) : "r"(saddr));
}
__device__ __forceinline__ void cp_async16(uint32_t saddr, const void* gaddr) {
    asm volatile("cp.async.cg.shared.global [%0], [%1], 16;" :: "r"(saddr), "l"(gaddr) : "memory");
}
#define CP_COMMIT()  asm volatile("cp.async.commit_group;" ::: "memory")
#define CP_WAIT1()   asm volatile("cp.async.wait_group 1;" ::: "memory")

// ---------------- unified prep kernel ----------------
#define TB_TOTAL 5760
#define PREP_BLOCKS 6785
__global__ void __launch_bounds__(256)
prep_kernel(const float* __restrict__ det,
            const float* __restrict__ W1,
            const float* __restrict__ W2,
            const float* __restrict__ W3,
            const float* __restrict__ R2,
            const float* __restrict__ cw)
{
    const int bid = blockIdx.x;
    if (bid < TB_TOTAL) {
        const float* src; __half* dst; int K, N, t;
        if (bid < 2048)      { src = W1;                        dst = g_W1t;                        K = 2048; N = 1024; t = bid; }
        else if (bid < 4096) { src = W1 + (size_t)2048 * 1024;  dst = g_W1t + (size_t)1024 * 2048;  K = 2048; N = 1024; t = bid - 2048; }
        else if (bid < 5120) { src = W2;                        dst = g_W2t;                        K = 1024; N = 1024; t = bid - 4096; }
        else if (bid < 5632) { src = W3;                        dst = g_W3t;                        K = 1024; N = 512;  t = bid - 5120; }
        else                 { src = R2;                        dst = g_R2t;                        K = 256;  N = 512;  t = bid - 5632; }
        const int tilesX = N >> 5;
        const int nb = (t % tilesX) << 5;
        const int kb = (t / tilesX) << 5;
        __shared__ float tt[32][33];
        const int x = threadIdx.x & 31;
        const int y = threadIdx.x >> 5;
#pragma unroll
        for (int i = y; i < 32; i += 8) tt[i][x] = src[(size_t)(kb + i) * N + nb + x];
        __syncthreads();
#pragma unroll
        for (int i = y; i < 32; i += 8)
            dst[(size_t)(nb + i) * K + kb + x] = __float2half_rn(tt[x][i]);
    } else if (bid < 6528) {
        const int row = bid - TB_TOTAL;
        const float* s = det + (size_t)row * 2048;
        __half* d = g_deth + (size_t)row * 2048;
#pragma unroll
        for (int j = 0; j < 8; ++j) {
            int k = threadIdx.x + j * 256;
            d[k] = __float2half_rn(s[k]);
        }
    } else if (bid < 6784) {
        int i = (bid - 6528) * 256 + threadIdx.x;
        int n = i >> 9, k = i & 511;
        g_cwp[i] = (n < NB) ? __float2half_rn(cw[(size_t)n * 512 + k]) : __float2half_rn(0.f);
    } else {
        if (threadIdx.x == 0) {
            g_acc[0] = 0.0; g_acc[1] = 0.0; g_acc[2] = 0.0;
            g_cnt[0] = 0u;  g_cnt[1] = 0u;
        }
    }
}

__device__ __forceinline__ float focal_loss(float x, float t) {
    float p  = 1.0f / (1.0f + expf(-x));
    float ce = fmaxf(x, 0.0f) - x * t + log1pf(expf(-fabsf(x)));
    float pt = p * t + (1.0f - p) * (1.0f - t);
    float om = 1.0f - pt;
    float at = 0.25f * t + 0.75f * (1.0f - t);
    return at * ce * om * om;
}

#define TROWB 144
#define ATILE (128 * TROWB)               // 18432
#define BTILE (256 * TROWB)               // 36864
#define STAGEW (ATILE + BTILE)            // 55296
#define NSTAGEW 3
#define GEMM_SMEMW (NSTAGEW * STAGEW)     // 165888

// =====================================================================
// WIDE fp16 GEMM: CTA 128x256, 512 threads (16 warps, 4/SMSP),
// warp tile 64x32, K-chunk 64, 3 stages (R15, unchanged).
// =====================================================================
template<int MODE>
__global__ void __launch_bounds__(512)
mma_gemmW(int K,
          const void* __restrict__ Ain, int lda,
          const __half* __restrict__ Bt,
          void* __restrict__ Cout, int ldc,
          const float* __restrict__ b1, const float* __restrict__ b2,
          const int* __restrict__ sids, const int* __restrict__ oids)
{
    extern __shared__ char smem[];
    __shared__ int urow[128], vrow[128];
    __shared__ float rps[128 * 12];

    const int tid  = threadIdx.x;
    const int wid  = tid >> 5;
    const int lane = tid & 31;
    const int rowBlk = blockIdx.y * 128;
    const int colBlk = blockIdx.x * 256;

    const int wm = (wid & 1) * 64;
    const int wn = (wid >> 1) * 32;
    const int g  = lane >> 2;
    const int tg = lane & 3;

    const uint32_t sb = smem_to_u32(smem);

    const __half* Ah = (const __half*)Ain;
    const float*  Af = (const float*)Ain;
    float*  Cf = (float*)Cout;
    __half* Ch = (__half*)Cout;

    if (MODE == 1) {
        if (tid < 128) {
            int r = rowBlk + tid;
            int b = r / PPB, p = r - b * PPB;
            urow[tid] = b * NDET + sids[p];
            vrow[tid] = b * NDET + oids[p];
        }
        __syncthreads();
    }
    if (MODE == 2) {
        for (int idx = tid; idx < 128 * 12; idx += 512)
            rps[idx] = Af[(size_t)rowBlk * 12 + idx];
        __syncthreads();
    }

    float acc[4][4][4];
#pragma unroll
    for (int i = 0; i < 4; i++)
#pragma unroll
        for (int j = 0; j < 4; j++)
#pragma unroll
            for (int q = 0; q < 4; q++) acc[i][j][q] = 0.f;

    int amr[2], aq[2];
#pragma unroll
    for (int j = 0; j < 2; ++j) {
        int idx = tid + j * 512;
        amr[j] = idx >> 3;
        aq[j]  = idx & 7;
    }

    uint4 ua[2], va[2];
    float4 rf[2][2];

    auto loadA = [&](int c) {
        const int k0 = c * 64;
#pragma unroll
        for (int j = 0; j < 2; ++j) {
            const int m = amr[j], base = k0 + aq[j] * 8;
            if (MODE == 1) {
                ua[j] = *reinterpret_cast<const uint4*>(&g_UVh[(size_t)urow[m] * 2048 + base]);
                va[j] = *reinterpret_cast<const uint4*>(&g_UVh[(size_t)vrow[m] * 2048 + 1024 + base]);
            } else if (MODE == 2) {
                float4 a0 = *reinterpret_cast<const float4*>(b2 + base);
                float4 a1 = *reinterpret_cast<const float4*>(b2 + base + 4);
#pragma unroll
                for (int t = 0; t < 12; ++t) {
                    const float xv = rps[m * 12 + t];
                    const float4 w0 = *reinterpret_cast<const float4*>(b1 + t * 256 + base);
                    const float4 w1 = *reinterpret_cast<const float4*>(b1 + t * 256 + base + 4);
                    a0.x = fmaf(xv, w0.x, a0.x); a0.y = fmaf(xv, w0.y, a0.y);
                    a0.z = fmaf(xv, w0.z, a0.z); a0.w = fmaf(xv, w0.w, a0.w);
                    a1.x = fmaf(xv, w1.x, a1.x); a1.y = fmaf(xv, w1.y, a1.y);
                    a1.z = fmaf(xv, w1.z, a1.z); a1.w = fmaf(xv, w1.w, a1.w);
                }
                a0.x = fmaxf(a0.x, 0.f); a0.y = fmaxf(a0.y, 0.f);
                a0.z = fmaxf(a0.z, 0.f); a0.w = fmaxf(a0.w, 0.f);
                a1.x = fmaxf(a1.x, 0.f); a1.y = fmaxf(a1.y, 0.f);
                a1.z = fmaxf(a1.z, 0.f); a1.w = fmaxf(a1.w, 0.f);
                rf[j][0] = a0; rf[j][1] = a1;
            }
        }
    };
    auto storeA = [&](int s) {
#pragma unroll
        for (int j = 0; j < 2; ++j) {
            const int m = amr[j], q = aq[j];
            uint4 h;
            if (MODE == 1) {
                h.x = hadd_relu2(ua[j].x, va[j].x);
                h.y = hadd_relu2(ua[j].y, va[j].y);
                h.z = hadd_relu2(ua[j].z, va[j].z);
                h.w = hadd_relu2(ua[j].w, va[j].w);
            } else {
                h.x = f2h2(rf[j][0].x, rf[j][0].y);
                h.y = f2h2(rf[j][0].z, rf[j][0].w);
                h.z = f2h2(rf[j][1].x, rf[j][1].y);
                h.w = f2h2(rf[j][1].z, rf[j][1].w);
            }
            *reinterpret_cast<uint4*>(smem + s * STAGEW + m * TROWB + q * 16) = h;
        }
    };
    auto issueLoads = [&](int c, int s) {
        const int k0 = c * 64;
#pragma unroll
        for (int j = 0; j < 4; ++j) {
            int idx = tid + j * 512;
            int m = idx >> 3, q = idx & 7;
            cp_async16(sb + (uint32_t)s * STAGEW + ATILE + (uint32_t)m * TROWB + (uint32_t)q * 16,
                       Bt + (size_t)(colBlk + m) * K + k0 + q * 8);
        }
        if (MODE == 0 || MODE == 4) {
#pragma unroll
            for (int j = 0; j < 2; ++j) {
                const int m = amr[j], q = aq[j];
                cp_async16(sb + (uint32_t)s * STAGEW + (uint32_t)m * TROWB + (uint32_t)q * 16,
                           Ah + (size_t)(rowBlk + m) * lda + k0 + q * 8);
            }
        }
    };

    const int laneRow  = lane & 15;
    const int laneColB = (lane >> 4) * 16;
    const uint32_t aFragBase = sb + (uint32_t)(wm + laneRow) * TROWB + laneColB;
    const uint32_t bFragBase = sb + ATILE + (uint32_t)(wn + laneRow) * TROWB + laneColB;

    auto compute = [&](int s) {
        const uint32_t aB = aFragBase + (uint32_t)s * STAGEW;
        const uint32_t bB = bFragBase + (uint32_t)s * STAGEW;
#pragma unroll
        for (int ks = 0; ks < 4; ++ks) {
            const uint32_t ko = (uint32_t)ks * 32;
            uint32_t a[4][4], bb[2][4];
#pragma unroll
            for (int mt = 0; mt < 4; ++mt) ldsm_x4(a[mt], aB + (uint32_t)mt * 2304 + ko);
#pragma unroll
            for (int n2 = 0; n2 < 2; ++n2)  ldsm_x4(bb[n2], bB + (uint32_t)n2 * 2304 + ko);
#pragma unroll
            for (int mt = 0; mt < 4; ++mt)
#pragma unroll
                for (int nt = 0; nt < 4; ++nt)
                    mma16816(acc[mt][nt], a[mt][0], a[mt][1], a[mt][2], a[mt][3],
                             bb[nt >> 1][nt & 1], bb[nt >> 1][2 + (nt & 1)]);
        }
    };

    const int nch = K >> 6;
    const bool FEED = (MODE == 1 || MODE == 2);

    if (FEED) loadA(0);
    issueLoads(0, 0); CP_COMMIT();
    if (FEED) { storeA(0); loadA(1); }
    issueLoads(1, 1); CP_COMMIT();
    CP_WAIT1();
    __syncthreads();

    for (int c = 0; c < nch; ++c) {
        const int s = c % 3;
        if (FEED) {
            if (c + 1 < nch) storeA((c + 1) % 3);
            if (c + 2 < nch) { loadA(c + 2); issueLoads(c + 2, (c + 2) % 3); }
        } else {
            if (c + 2 < nch) issueLoads(c + 2, (c + 2) % 3);
        }
        CP_COMMIT();
        compute(s);
        CP_WAIT1();
        __syncthreads();
    }

    if (MODE == 0) {
#pragma unroll
        for (int mt = 0; mt < 4; ++mt) {
#pragma unroll
            for (int nt = 0; nt < 4; ++nt) {
                const int col = colBlk + wn + nt * 8 + 2 * tg;
                const int row0 = rowBlk + wm + mt * 16 + g;
                *reinterpret_cast<float2*>(Cf + (size_t)row0 * ldc + col) =
                    make_float2(acc[mt][nt][0], acc[mt][nt][1]);
                *reinterpret_cast<float2*>(Cf + (size_t)(row0 + 8) * ldc + col) =
                    make_float2(acc[mt][nt][2], acc[mt][nt][3]);
            }
        }
    } else if (MODE == 1) {
#pragma unroll
        for (int mt = 0; mt < 4; ++mt) {
#pragma unroll
            for (int nt = 0; nt < 4; ++nt) {
                const int col = colBlk + wn + nt * 8 + 2 * tg;
                const float2 bb = *reinterpret_cast<const float2*>(b2 + col);
                const int row0 = rowBlk + wm + mt * 16 + g;
                uint32_t h0 = f2h2(fmaxf(acc[mt][nt][0] + bb.x, 0.f),
                                   fmaxf(acc[mt][nt][1] + bb.y, 0.f));
                uint32_t h1 = f2h2(fmaxf(acc[mt][nt][2] + bb.x, 0.f),
                                   fmaxf(acc[mt][nt][3] + bb.y, 0.f));
                *reinterpret_cast<uint32_t*>(Ch + (size_t)row0 * ldc + col)       = h0;
                *reinterpret_cast<uint32_t*>(Ch + (size_t)(row0 + 8) * ldc + col) = h1;
            }
        }
    } else {  // MODE 2 / 4
#pragma unroll
        for (int mt = 0; mt < 4; ++mt) {
#pragma unroll
            for (int nt = 0; nt < 4; ++nt) {
                const int col = colBlk + wn + nt * 8 + 2 * tg;
                float bx = 0.f, by = 0.f;
                if (MODE == 4 && col < 1024) {
                    const float2 bb = *reinterpret_cast<const float2*>(b1 + col);
                    bx = bb.x; by = bb.y;
                }
                const int row0 = rowBlk + wm + mt * 16 + g;
                uint32_t h0 = f2h2(acc[mt][nt][0] + bx, acc[mt][nt][1] + by);
                uint32_t h1 = f2h2(acc[mt][nt][2] + bx, acc[mt][nt][3] + by);
                *reinterpret_cast<uint32_t*>(Ch + (size_t)row0 * ldc + col)       = h0;
                *reinterpret_cast<uint32_t*>(Ch + (size_t)(row0 + 8) * ldc + col) = h1;
            }
        }
    }
}

// =====================================================================
// FUSED normalize + logits GEMM + focal + distil.
// 256 threads / 8 warps; each warp normalizes 16 rows of sp/re into the
// smem A tiles (all 8 K-chunks resident), accumulates distil, then runs
// the 128x128 logits GEMM (B = cwp streamed 3-stage) + focal reduction.
// smem: A[8][ATILE] = 147456, B[3][ATILE] = 55296 -> 202752 bytes.
// =====================================================================
#define LOG_SMEM (8 * ATILE + 3 * ATILE)   // 202752

__global__ void __launch_bounds__(256)
mma_logits_fused(const __half* __restrict__ Bt,
                 const float* __restrict__ traj,
                 const int* __restrict__ sids,
                 const int* __restrict__ oids,
                 const int* __restrict__ labels,
                 const float* __restrict__ temp)
{
    extern __shared__ char smem[];
    __shared__ float wredP[8], wredN[8], wredD[8];
    __shared__ int   wpc[8], wnc[8];

    const int tid  = threadIdx.x;
    const int wid  = tid >> 5;
    const int lane = tid & 31;
    const int rowBlk = blockIdx.y * 128;
    const int K = 512;

    const int wm = (wid & 1) * 64;
    const int wn = (wid >> 1) * 32;
    const int g  = lane >> 2;
    const int tg = lane & 3;

    const uint32_t sb  = smem_to_u32(smem);
    const uint32_t sbB = sb + 8 * ATILE;

    // ---- phase 1: normalize rows into smem A chunks + distil ----
    const int chunkOfLane = lane >> 2;              // cols lane*16.. -> chunk
    const uint32_t laneByte = (uint32_t)(lane & 3) * 32;
    float dacc = 0.f;
#pragma unroll 1
    for (int i = 0; i < 16; ++i) {
        const int rl = wid * 16 + i;
        const int r  = rowBlk + rl;

        float sp[16], re[16];
        {
            const float4* spv = reinterpret_cast<const float4*>(g_sp + (size_t)r * 512) + lane * 4;
            const uint4*  rev = reinterpret_cast<const uint4*>(g_reh + (size_t)r * 512) + lane * 2;
#pragma unroll
            for (int q = 0; q < 4; ++q) {
                float4 v = spv[q];
                sp[q * 4 + 0] = v.x; sp[q * 4 + 1] = v.y; sp[q * 4 + 2] = v.z; sp[q * 4 + 3] = v.w;
            }
#pragma unroll
            for (int q = 0; q < 2; ++q) {
                uint4 u = rev[q];
                const __half2* h = reinterpret_cast<const __half2*>(&u);
#pragma unroll
                for (int j = 0; j < 4; ++j) {
                    float2 f = __half22float2(h[j]);
                    re[q * 8 + j * 2]     = f.x;
                    re[q * 8 + j * 2 + 1] = f.y;
                }
            }
        }
        float ssp = 0.f, sre = 0.f;
#pragma unroll
        for (int q = 0; q < 16; ++q) { ssp += sp[q] * sp[q]; sre += re[q] * re[q]; }
#pragma unroll
        for (int o = 16; o > 0; o >>= 1) {
            ssp += __shfl_xor_sync(0xffffffffu, ssp, o);
            sre += __shfl_xor_sync(0xffffffffu, sre, o);
        }
        const float inv_sp = 1.f / fmaxf(sqrtf(ssp), 1e-12f);
        const float inv_re = 1.f / fmaxf(sqrtf(sre), 1e-12f);

        float comb[16];
        float ssc = 0.f;
#pragma unroll
        for (int q = 0; q < 16; ++q) {
            comb[q] = sp[q] * inv_sp + re[q] * inv_re;
            ssc += comb[q] * comb[q];
        }
#pragma unroll
        for (int o = 16; o > 0; o >>= 1) ssc += __shfl_xor_sync(0xffffffffu, ssc, o);
        const float inv_c = 1.f / fmaxf(sqrtf(ssc), 1e-12f);

        {
            uint4 u[2];
            uint32_t* w = reinterpret_cast<uint32_t*>(u);
#pragma unroll
            for (int j = 0; j < 8; ++j)
                w[j] = f2h2(comb[j * 2] * inv_c, comb[j * 2 + 1] * inv_c);
            char* dst = smem + chunkOfLane * ATILE + rl * TROWB + laneByte;
            *reinterpret_cast<uint4*>(dst)      = u[0];
            *reinterpret_cast<uint4*>(dst + 16) = u[1];
        }

        const int b = r / PPB;
        const int p = r - b * PPB;
        const float* tr = (lane < 16)
            ? traj + ((size_t)b * NDET + sids[p]) * 256 + lane * 16
            : traj + ((size_t)b * NDET + oids[p]) * 256 + (lane - 16) * 16;
        float d = 0.f;
#pragma unroll
        for (int q = 0; q < 16; ++q) d += fabsf(tr[q] - sp[q]);
        dacc += d;
    }
#pragma unroll
    for (int o = 16; o > 0; o >>= 1) dacc += __shfl_xor_sync(0xffffffffu, dacc, o);
    if (lane == 0) wredD[wid] = dacc;
    __syncthreads();

    // ---- phase 2: logits GEMM (A in smem chunks, B streamed) ----
    float acc[4][4][4];
#pragma unroll
    for (int i = 0; i < 4; i++)
#pragma unroll
        for (int j = 0; j < 4; j++)
#pragma unroll
            for (int q = 0; q < 4; q++) acc[i][j][q] = 0.f;

    int amr[4], aq[4];
#pragma unroll
    for (int j = 0; j < 4; ++j) {
        int idx = tid + j * 256;
        amr[j] = idx >> 3;
        aq[j]  = idx & 7;
    }

    auto issueB = [&](int c, int s) {
        const int k0 = c * 64;
#pragma unroll
        for (int j = 0; j < 4; ++j) {
            const int m = amr[j], q = aq[j];
            cp_async16(sbB + (uint32_t)s * ATILE + (uint32_t)m * TROWB + (uint32_t)q * 16,
                       Bt + (size_t)m * K + k0 + q * 8);
        }
    };

    const int laneRow  = lane & 15;
    const int laneColB = (lane >> 4) * 16;
    const uint32_t aFragBase = sb + (uint32_t)(wm + laneRow) * TROWB + laneColB;
    const uint32_t bFragBase = sbB + (uint32_t)(wn + laneRow) * TROWB + laneColB;

    auto compute = [&](int c, int s) {
        const uint32_t aB = aFragBase + (uint32_t)c * ATILE;
        const uint32_t bB = bFragBase + (uint32_t)s * ATILE;
#pragma unroll
        for (int ks = 0; ks < 4; ++ks) {
            const uint32_t ko = (uint32_t)ks * 32;
            uint32_t a[4][4], bb[2][4];
#pragma unroll
            for (int mt = 0; mt < 4; ++mt) ldsm_x4(a[mt], aB + (uint32_t)mt * 2304 + ko);
#pragma unroll
            for (int n2 = 0; n2 < 2; ++n2)  ldsm_x4(bb[n2], bB + (uint32_t)n2 * 2304 + ko);
#pragma unroll
            for (int mt = 0; mt < 4; ++mt)
#pragma unroll
                for (int nt = 0; nt < 4; ++nt)
                    mma16816(acc[mt][nt], a[mt][0], a[mt][1], a[mt][2], a[mt][3],
                             bb[nt >> 1][nt & 1], bb[nt >> 1][2 + (nt & 1)]);
        }
    };

    const int nch = K >> 6;   // 8
    issueB(0, 0); CP_COMMIT();
    issueB(1, 1); CP_COMMIT();
    CP_WAIT1();
    __syncthreads();
    for (int c = 0; c < nch; ++c) {
        const int s = c % 3;
        if (c + 2 < nch) issueB(c + 2, (c + 2) % 3);
        CP_COMMIT();
        compute(c, s);
        CP_WAIT1();
        __syncthreads();
    }

    // ---- phase 3: stage logits, focal reduction ----
    float* stageL = reinterpret_cast<float*>(smem);    // [128][132] (reuses A chunks 0..3)
#pragma unroll
    for (int mt = 0; mt < 4; ++mt) {
#pragma unroll
        for (int nt = 0; nt < 4; ++nt) {
            const int col = wn + nt * 8 + 2 * tg;
            const int r0  = wm + mt * 16 + g;
            *reinterpret_cast<float2*>(&stageL[r0 * 132 + col]) =
                make_float2(acc[mt][nt][0], acc[mt][nt][1]);
            *reinterpret_cast<float2*>(&stageL[(r0 + 8) * 132 + col]) =
                make_float2(acc[mt][nt][2], acc[mt][nt][3]);
        }
    }
    __syncthreads();

    const float inv_t = 1.0f / temp[0];
    float flp = 0.f, fln = 0.f;
    int pc = 0, nc = 0;
#pragma unroll 1
    for (int i = 0; i < 16; ++i) {
        const int r = wid * 16 + i;
        const int* lab = labels + (size_t)(rowBlk + r) * NLAB;
        const int l0 = lab[0];
        float fp = 0.f, fn = 0.f;
        bool any = false;
        for (int c = lane; c < NB; c += 32) {
            const int t = lab[1 + c];
            const float x = stageL[r * 132 + c] * inv_t;
            fp += focal_loss(x, (float)t);
            fn += focal_loss(x, 0.f);
            any |= (t > 0);
        }
#pragma unroll
        for (int o = 16; o > 0; o >>= 1) {
            fp += __shfl_xor_sync(0xffffffffu, fp, o);
            fn += __shfl_xor_sync(0xffffffffu, fn, o);
        }
        const bool pos = __any_sync(0xffffffffu, any);
        const bool neg = (l0 > 0);
        if (lane == 0) {
            if (pos) { flp += fp; pc++; }
            if (neg) { fln += fn; nc++; }
        }
    }
    if (lane == 0) { wredP[wid] = flp; wredN[wid] = fln; wpc[wid] = pc; wnc[wid] = nc; }
    __syncthreads();
    if (tid == 0) {
        float sp = 0.f, sn = 0.f, sd = 0.f; int cp = 0, cn = 0;
#pragma unroll
        for (int w = 0; w < 8; ++w) {
            sp += wredP[w]; sn += wredN[w]; sd += wredD[w];
            cp += wpc[w]; cn += wnc[w];
        }
        atomicAdd(&g_acc[0], (double)sp);
        atomicAdd(&g_acc[1], (double)sn);
        atomicAdd(&g_acc[2], (double)sd);
        if (cp) atomicAdd(&g_cnt[0], (unsigned)cp);
        if (cn) atomicAdd(&g_cnt[1], (unsigned)cn);
    }
}

// ---------------- finalize ----------------
__global__ void finalize_kernel(float* __restrict__ out) {
    double pc = (double)(g_cnt[0] > 0u ? g_cnt[0] : 1u);
    double nc = (double)(g_cnt[1] > 0u ? g_cnt[1] : 1u);
    double total = g_acc[0] / (pc * (double)NB)
                 + g_acc[1] / (nc * (double)NB)
                 + g_acc[2] / ((double)MROWS * 512.0);
    out[0] = (float)total;
}

// ---------------- launch ----------------
extern "C" void kernel_launch(void* const* d_in, const int* in_sizes, int n_in,
                              void* d_out, int out_size)
{
    const float* det    = (const float*)d_in[0];
    const float* traj   = (const float*)d_in[1];
    const float* rp     = (const float*)d_in[2];
    const float* cw     = (const float*)d_in[3];
    const float* W1     = (const float*)d_in[4];
    const float* b1     = (const float*)d_in[5];
    const float* W2     = (const float*)d_in[6];
    const float* b2     = (const float*)d_in[7];
    const float* W3     = (const float*)d_in[8];
    const float* R1     = (const float*)d_in[9];
    const float* rb1    = (const float*)d_in[10];
    const float* R2     = (const float*)d_in[11];
    const float* temp   = (const float*)d_in[12];
    const int*   labels = (const int*)d_in[13];
    const int*   sids   = (const int*)d_in[14];
    const int*   oids   = (const int*)d_in[15];
    float* out = (float*)d_out;

    void *p_deth, *p_uvh, *p_h2h, *p_sp, *p_reh,
         *p_w1t, *p_w2t, *p_w3t, *p_r2t, *p_cwp;
    cudaGetSymbolAddress(&p_deth, g_deth);
    cudaGetSymbolAddress(&p_uvh, g_UVh);
    cudaGetSymbolAddress(&p_h2h, g_h2h);
    cudaGetSymbolAddress(&p_sp, g_sp);
    cudaGetSymbolAddress(&p_reh, g_reh);
    cudaGetSymbolAddress(&p_w1t, g_W1t);
    cudaGetSymbolAddress(&p_w2t, g_W2t);
    cudaGetSymbolAddress(&p_w3t, g_W3t);
    cudaGetSymbolAddress(&p_r2t, g_R2t);
    cudaGetSymbolAddress(&p_cwp, g_cwp);
    __half* DETH  = (__half*)p_deth;
    __half* UVH   = (__half*)p_uvh;
    __half* H2H   = (__half*)p_h2h;
    float*  SP    = (float*)p_sp;
    __half* REH   = (__half*)p_reh;
    __half* W1T   = (__half*)p_w1t;
    __half* W2T   = (__half*)p_w2t;
    __half* W3T   = (__half*)p_w3t;
    __half* R2T   = (__half*)p_r2t;

    cudaFuncSetAttribute(mma_gemmW<0>, cudaFuncAttributeMaxDynamicSharedMemorySize, GEMM_SMEMW);
    cudaFuncSetAttribute(mma_gemmW<1>, cudaFuncAttributeMaxDynamicSharedMemorySize, GEMM_SMEMW);
    cudaFuncSetAttribute(mma_gemmW<2>, cudaFuncAttributeMaxDynamicSharedMemorySize, GEMM_SMEMW);
    cudaFuncSetAttribute(mma_gemmW<4>, cudaFuncAttributeMaxDynamicSharedMemorySize, GEMM_SMEMW);
    cudaFuncSetAttribute(mma_logits_fused, cudaFuncAttributeMaxDynamicSharedMemorySize, LOG_SMEM);

    // ALL prep in one launch
    prep_kernel<<<PREP_BLOCKS, 256>>>(det, W1, W2, W3, R2, cw);

    // UV' = det @ [W1U | W1V]  (fp16, +b1 on U half)
    mma_gemmW<4><<<dim3(8, 6), 512, GEMM_SMEMW>>>(2048, DETH, 2048, W1T, UVH, 2048,
                                                  b1, nullptr, nullptr, nullptr);
    // h2 = relu(relu(U'_s + V_o) @ W2 + b2)  (fp16)
    mma_gemmW<1><<<dim3(4, MROWS / 128), 512, GEMM_SMEMW>>>(1024, nullptr, 0, W2T, H2H, 1024,
                                                            nullptr, b2, sids, oids);
    // so_proj = h2 @ W3   (fp32)
    mma_gemmW<0><<<dim3(2, MROWS / 128), 512, GEMM_SMEMW>>>(1024, H2H, 1024, W3T, SP, 512,
                                                            nullptr, nullptr, nullptr, nullptr);
    // re = relu(rp @ R1 + rb1) @ R2   (fp16)
    mma_gemmW<2><<<dim3(2, MROWS / 128), 512, GEMM_SMEMW>>>(256, rp, 12, R2T, REH, 512,
                                                            R1, rb1, nullptr, nullptr);
    // fused normalize + logits + focal + distil
    mma_logits_fused<<<dim3(1, MROWS / 128), 256, LOG_SMEM>>>((__half*)p_cwp, traj, sids, oids,
                                                              labels, temp);
    finalize_kernel<<<1, 1>>>(out);
}

// round 17
// speedup vs baseline: 1.0722x; 1.0722x over previous
#include <cuda_runtime.h>
#include <cuda_fp16.h>
#include <math.h>
#include <cstdint>

// ---------------- problem constants ----------------
#define PPB   2256
#define MROWS 36096
#define NDET  48
#define NB    92
#define NLAB  133

// ---------------- scratch ----------------
__device__ __half g_deth[768 * 2048];
__device__ __half g_UVh[768 * 2048];                  // U'(=U+b1) | V
__device__ __half g_h2h[(size_t)MROWS * 1024];
__device__ __half g_sph[(size_t)MROWS * 512];         // so_proj (fp16)
__device__ __half g_reh[(size_t)MROWS * 512];
__device__ __half g_combh[(size_t)MROWS * 512];
__device__ __half g_W1t[2048 * 2048];
__device__ __half g_W2t[1024 * 1024];
__device__ __half g_W3t[512 * 1024];
__device__ __half g_R2t[512 * 256];
__device__ __half g_cwp[128 * 512];
__device__ double g_acc[3];
__device__ unsigned int g_cnt[2];

// ---------------- helpers ----------------
__device__ __forceinline__ uint32_t smem_to_u32(const void* p) {
    uint32_t a;
    asm("{ .reg .u64 t; cvta.to.shared.u64 t, %1; cvt.u32.u64 %0, t; }" : "=r"(a) : "l"(p));
    return a;
}
__device__ __forceinline__ uint32_t f2h2(float lo, float hi) {
    __half2 h = __floats2half2_rn(lo, hi);
    return *reinterpret_cast<uint32_t*>(&h);
}
__device__ __forceinline__ uint32_t hadd_relu2(uint32_t a, uint32_t b) {
    __half2 r = __hmax2(__hadd2(*reinterpret_cast<__half2*>(&a),
                                *reinterpret_cast<__half2*>(&b)),
                        __half2(__float2half_rn(0.f), __float2half_rn(0.f)));
    return *reinterpret_cast<uint32_t*>(&r);
}
__device__ __forceinline__ void mma16816(float* d,
                                         uint32_t a0, uint32_t a1, uint32_t a2, uint32_t a3,
                                         uint32_t b0, uint32_t b1) {
    asm volatile(
        "mma.sync.aligned.m16n8k16.row.col.f32.f16.f16.f32 "
        "{%0,%1,%2,%3}, {%4,%5,%6,%7}, {%8,%9}, {%0,%1,%2,%3};"
        : "+f"(d[0]), "+f"(d[1]), "+f"(d[2]), "+f"(d[3])
        : "r"(a0), "r"(a1), "r"(a2), "r"(a3), "r"(b0), "r"(b1));
}
__device__ __forceinline__ void ldsm_x4(uint32_t* r, uint32_t saddr) {
    asm volatile("ldmatrix.sync.aligned.m8n8.x4.shared.b16 {%0,%1,%2,%3}, [%4];"
                 : "=r"(r[0]), "=r"(r[1]), "=r"(r[2]), "=r"(r[3]) : "r"(saddr));
}
__device__ __forceinline__ void cp_async16(uint32_t saddr, const void* gaddr) {
    asm volatile("cp.async.cg.shared.global [%0], [%1], 16;" :: "r"(saddr), "l"(gaddr) : "memory");
}
#define CP_COMMIT()  asm volatile("cp.async.commit_group;" ::: "memory")
#define CP_WAIT1()   asm volatile("cp.async.wait_group 1;" ::: "memory")

// ---------------- unified prep kernel ----------------
#define TB_TOTAL 5760
#define PREP_BLOCKS 6785
__global__ void __launch_bounds__(256)
prep_kernel(const float* __restrict__ det,
            const float* __restrict__ W1,
            const float* __restrict__ W2,
            const float* __restrict__ W3,
            const float* __restrict__ R2,
            const float* __restrict__ cw)
{
    const int bid = blockIdx.x;
    if (bid < TB_TOTAL) {
        const float* src; __half* dst; int K, N, t;
        if (bid < 2048)      { src = W1;                        dst = g_W1t;                        K = 2048; N = 1024; t = bid; }
        else if (bid < 4096) { src = W1 + (size_t)2048 * 1024;  dst = g_W1t + (size_t)1024 * 2048;  K = 2048; N = 1024; t = bid - 2048; }
        else if (bid < 5120) { src = W2;                        dst = g_W2t;                        K = 1024; N = 1024; t = bid - 4096; }
        else if (bid < 5632) { src = W3;                        dst = g_W3t;                        K = 1024; N = 512;  t = bid - 5120; }
        else                 { src = R2;                        dst = g_R2t;                        K = 256;  N = 512;  t = bid - 5632; }
        const int tilesX = N >> 5;
        const int nb = (t % tilesX) << 5;
        const int kb = (t / tilesX) << 5;
        __shared__ float tt[32][33];
        const int x = threadIdx.x & 31;
        const int y = threadIdx.x >> 5;
#pragma unroll
        for (int i = y; i < 32; i += 8) tt[i][x] = src[(size_t)(kb + i) * N + nb + x];
        __syncthreads();
#pragma unroll
        for (int i = y; i < 32; i += 8)
            dst[(size_t)(nb + i) * K + kb + x] = __float2half_rn(tt[x][i]);
    } else if (bid < 6528) {
        const int row = bid - TB_TOTAL;
        const float* s = det + (size_t)row * 2048;
        __half* d = g_deth + (size_t)row * 2048;
#pragma unroll
        for (int j = 0; j < 8; ++j) {
            int k = threadIdx.x + j * 256;
            d[k] = __float2half_rn(s[k]);
        }
    } else if (bid < 6784) {
        int i = (bid - 6528) * 256 + threadIdx.x;
        int n = i >> 9, k = i & 511;
        g_cwp[i] = (n < NB) ? __float2half_rn(cw[(size_t)n * 512 + k]) : __float2half_rn(0.f);
    } else {
        if (threadIdx.x == 0) {
            g_acc[0] = 0.0; g_acc[1] = 0.0; g_acc[2] = 0.0;
            g_cnt[0] = 0u;  g_cnt[1] = 0u;
        }
    }
}

__device__ __forceinline__ float focal_loss(float x, float t) {
    float p  = 1.0f / (1.0f + expf(-x));
    float ce = fmaxf(x, 0.0f) - x * t + log1pf(expf(-fabsf(x)));
    float pt = p * t + (1.0f - p) * (1.0f - t);
    float om = 1.0f - pt;
    float at = 0.25f * t + 0.75f * (1.0f - t);
    return at * ce * om * om;
}

#define TROWB 144
#define ATILE (128 * TROWB)               // 18432
#define BTILE (256 * TROWB)               // 36864
#define STAGEW (ATILE + BTILE)            // 55296
#define NSTAGEW 3
#define GEMM_SMEMW (NSTAGEW * STAGEW)     // 165888

// =====================================================================
// WIDE fp16 GEMM: CTA 128x256, 512 threads (16 warps, 4/SMSP),
// warp tile 64x32, K-chunk 64, 3 stages (R15 structure).
// MODE 1: A = relu(U'[urow] + V[vrow]) from g_UVh; C = half relu(+b2).
// MODE 2: A = half(relu(rp @ R1 + rb1)); C = fp16. (Ain=rp, b1=R1, b2=rb1)
// MODE 4: A = half gmem (cp.async); C = fp16, +b1 on cols<1024 iff b1!=null.
// =====================================================================
template<int MODE>
__global__ void __launch_bounds__(512)
mma_gemmW(int K,
          const void* __restrict__ Ain, int lda,
          const __half* __restrict__ Bt,
          void* __restrict__ Cout, int ldc,
          const float* __restrict__ b1, const float* __restrict__ b2,
          const int* __restrict__ sids, const int* __restrict__ oids)
{
    extern __shared__ char smem[];
    __shared__ int urow[128], vrow[128];
    __shared__ float rps[128 * 12];

    const int tid  = threadIdx.x;
    const int wid  = tid >> 5;
    const int lane = tid & 31;
    const int rowBlk = blockIdx.y * 128;
    const int colBlk = blockIdx.x * 256;

    const int wm = (wid & 1) * 64;
    const int wn = (wid >> 1) * 32;
    const int g  = lane >> 2;
    const int tg = lane & 3;

    const uint32_t sb = smem_to_u32(smem);

    const __half* Ah = (const __half*)Ain;
    const float*  Af = (const float*)Ain;
    __half* Ch = (__half*)Cout;

    if (MODE == 1) {
        if (tid < 128) {
            int r = rowBlk + tid;
            int b = r / PPB, p = r - b * PPB;
            urow[tid] = b * NDET + sids[p];
            vrow[tid] = b * NDET + oids[p];
        }
        __syncthreads();
    }
    if (MODE == 2) {
        for (int idx = tid; idx < 128 * 12; idx += 512)
            rps[idx] = Af[(size_t)rowBlk * 12 + idx];
        __syncthreads();
    }

    float acc[4][4][4];
#pragma unroll
    for (int i = 0; i < 4; i++)
#pragma unroll
        for (int j = 0; j < 4; j++)
#pragma unroll
            for (int q = 0; q < 4; q++) acc[i][j][q] = 0.f;

    int amr[2], aq[2];
#pragma unroll
    for (int j = 0; j < 2; ++j) {
        int idx = tid + j * 512;
        amr[j] = idx >> 3;
        aq[j]  = idx & 7;
    }

    uint4 ua[2], va[2];
    float4 rf[2][2];

    auto loadA = [&](int c) {
        const int k0 = c * 64;
#pragma unroll
        for (int j = 0; j < 2; ++j) {
            const int m = amr[j], base = k0 + aq[j] * 8;
            if (MODE == 1) {
                ua[j] = *reinterpret_cast<const uint4*>(&g_UVh[(size_t)urow[m] * 2048 + base]);
                va[j] = *reinterpret_cast<const uint4*>(&g_UVh[(size_t)vrow[m] * 2048 + 1024 + base]);
            } else if (MODE == 2) {
                float4 a0 = *reinterpret_cast<const float4*>(b2 + base);
                float4 a1 = *reinterpret_cast<const float4*>(b2 + base + 4);
#pragma unroll
                for (int t = 0; t < 12; ++t) {
                    const float xv = rps[m * 12 + t];
                    const float4 w0 = *reinterpret_cast<const float4*>(b1 + t * 256 + base);
                    const float4 w1 = *reinterpret_cast<const float4*>(b1 + t * 256 + base + 4);
                    a0.x = fmaf(xv, w0.x, a0.x); a0.y = fmaf(xv, w0.y, a0.y);
                    a0.z = fmaf(xv, w0.z, a0.z); a0.w = fmaf(xv, w0.w, a0.w);
                    a1.x = fmaf(xv, w1.x, a1.x); a1.y = fmaf(xv, w1.y, a1.y);
                    a1.z = fmaf(xv, w1.z, a1.z); a1.w = fmaf(xv, w1.w, a1.w);
                }
                a0.x = fmaxf(a0.x, 0.f); a0.y = fmaxf(a0.y, 0.f);
                a0.z = fmaxf(a0.z, 0.f); a0.w = fmaxf(a0.w, 0.f);
                a1.x = fmaxf(a1.x, 0.f); a1.y = fmaxf(a1.y, 0.f);
                a1.z = fmaxf(a1.z, 0.f); a1.w = fmaxf(a1.w, 0.f);
                rf[j][0] = a0; rf[j][1] = a1;
            }
        }
    };
    auto storeA = [&](int s) {
#pragma unroll
        for (int j = 0; j < 2; ++j) {
            const int m = amr[j], q = aq[j];
            uint4 h;
            if (MODE == 1) {
                h.x = hadd_relu2(ua[j].x, va[j].x);
                h.y = hadd_relu2(ua[j].y, va[j].y);
                h.z = hadd_relu2(ua[j].z, va[j].z);
                h.w = hadd_relu2(ua[j].w, va[j].w);
            } else {
                h.x = f2h2(rf[j][0].x, rf[j][0].y);
                h.y = f2h2(rf[j][0].z, rf[j][0].w);
                h.z = f2h2(rf[j][1].x, rf[j][1].y);
                h.w = f2h2(rf[j][1].z, rf[j][1].w);
            }
            *reinterpret_cast<uint4*>(smem + s * STAGEW + m * TROWB + q * 16) = h;
        }
    };
    auto issueLoads = [&](int c, int s) {
        const int k0 = c * 64;
#pragma unroll
        for (int j = 0; j < 4; ++j) {
            int idx = tid + j * 512;
            int m = idx >> 3, q = idx & 7;
            cp_async16(sb + (uint32_t)s * STAGEW + ATILE + (uint32_t)m * TROWB + (uint32_t)q * 16,
                       Bt + (size_t)(colBlk + m) * K + k0 + q * 8);
        }
        if (MODE == 4) {
#pragma unroll
            for (int j = 0; j < 2; ++j) {
                const int m = amr[j], q = aq[j];
                cp_async16(sb + (uint32_t)s * STAGEW + (uint32_t)m * TROWB + (uint32_t)q * 16,
                           Ah + (size_t)(rowBlk + m) * lda + k0 + q * 8);
            }
        }
    };

    const int laneRow  = lane & 15;
    const int laneColB = (lane >> 4) * 16;
    const uint32_t aFragBase = sb + (uint32_t)(wm + laneRow) * TROWB + laneColB;
    const uint32_t bFragBase = sb + ATILE + (uint32_t)(wn + laneRow) * TROWB + laneColB;

    auto compute = [&](int s) {
        const uint32_t aB = aFragBase + (uint32_t)s * STAGEW;
        const uint32_t bB = bFragBase + (uint32_t)s * STAGEW;
#pragma unroll
        for (int ks = 0; ks < 4; ++ks) {
            const uint32_t ko = (uint32_t)ks * 32;
            uint32_t a[4][4], bb[2][4];
#pragma unroll
            for (int mt = 0; mt < 4; ++mt) ldsm_x4(a[mt], aB + (uint32_t)mt * 2304 + ko);
#pragma unroll
            for (int n2 = 0; n2 < 2; ++n2)  ldsm_x4(bb[n2], bB + (uint32_t)n2 * 2304 + ko);
#pragma unroll
            for (int mt = 0; mt < 4; ++mt)
#pragma unroll
                for (int nt = 0; nt < 4; ++nt)
                    mma16816(acc[mt][nt], a[mt][0], a[mt][1], a[mt][2], a[mt][3],
                             bb[nt >> 1][nt & 1], bb[nt >> 1][2 + (nt & 1)]);
        }
    };

    const int nch = K >> 6;
    const bool FEED = (MODE == 1 || MODE == 2);

    if (FEED) loadA(0);
    issueLoads(0, 0); CP_COMMIT();
    if (FEED) { storeA(0); loadA(1); }
    issueLoads(1, 1); CP_COMMIT();
    CP_WAIT1();
    __syncthreads();

    for (int c = 0; c < nch; ++c) {
        const int s = c % 3;
        if (FEED) {
            if (c + 1 < nch) storeA((c + 1) % 3);
            if (c + 2 < nch) { loadA(c + 2); issueLoads(c + 2, (c + 2) % 3); }
        } else {
            if (c + 2 < nch) issueLoads(c + 2, (c + 2) % 3);
        }
        CP_COMMIT();
        compute(s);
        CP_WAIT1();
        __syncthreads();
    }

    if (MODE == 1) {
#pragma unroll
        for (int mt = 0; mt < 4; ++mt) {
#pragma unroll
            for (int nt = 0; nt < 4; ++nt) {
                const int col = colBlk + wn + nt * 8 + 2 * tg;
                const float2 bb = *reinterpret_cast<const float2*>(b2 + col);
                const int row0 = rowBlk + wm + mt * 16 + g;
                uint32_t h0 = f2h2(fmaxf(acc[mt][nt][0] + bb.x, 0.f),
                                   fmaxf(acc[mt][nt][1] + bb.y, 0.f));
                uint32_t h1 = f2h2(fmaxf(acc[mt][nt][2] + bb.x, 0.f),
                                   fmaxf(acc[mt][nt][3] + bb.y, 0.f));
                *reinterpret_cast<uint32_t*>(Ch + (size_t)row0 * ldc + col)       = h0;
                *reinterpret_cast<uint32_t*>(Ch + (size_t)(row0 + 8) * ldc + col) = h1;
            }
        }
    } else {  // MODE 2 / 4
        const bool addb = (MODE == 4) && (b1 != nullptr);
#pragma unroll
        for (int mt = 0; mt < 4; ++mt) {
#pragma unroll
            for (int nt = 0; nt < 4; ++nt) {
                const int col = colBlk + wn + nt * 8 + 2 * tg;
                float bx = 0.f, by = 0.f;
                if (addb && col < 1024) {
                    const float2 bb = *reinterpret_cast<const float2*>(b1 + col);
                    bx = bb.x; by = bb.y;
                }
                const int row0 = rowBlk + wm + mt * 16 + g;
                uint32_t h0 = f2h2(acc[mt][nt][0] + bx, acc[mt][nt][1] + by);
                uint32_t h1 = f2h2(acc[mt][nt][2] + bx, acc[mt][nt][3] + by);
                *reinterpret_cast<uint32_t*>(Ch + (size_t)row0 * ldc + col)       = h0;
                *reinterpret_cast<uint32_t*>(Ch + (size_t)(row0 + 8) * ldc + col) = h1;
            }
        }
    }
}

// =====================================================================
// Logits GEMM + fused focal (proven R11/R15 128x128 kernel)
// =====================================================================
#define TILE_BYTES (128 * TROWB)
#define NSTAGE 3
#define GEMM_SMEM (2 * NSTAGE * TILE_BYTES)

__global__ void __launch_bounds__(256)
mma_logits(const __half* __restrict__ Ah,
           const __half* __restrict__ Bt,
           const int* __restrict__ labels, const float* __restrict__ temp)
{
    extern __shared__ char smem[];
    __shared__ float wredP[8], wredN[8];
    __shared__ int   wpc[8], wnc[8];

    const int tid  = threadIdx.x;
    const int wid  = tid >> 5;
    const int lane = tid & 31;
    const int rowBlk = blockIdx.y * 128;
    const int K = 512;

    const int wm = (wid & 1) * 64;
    const int wn = (wid >> 1) * 32;
    const int g  = lane >> 2;
    const int tg = lane & 3;

    const uint32_t sb  = smem_to_u32(smem);
    const uint32_t sbA = sb;
    const uint32_t sbB = sb + NSTAGE * TILE_BYTES;

    float acc[4][4][4];
#pragma unroll
    for (int i = 0; i < 4; i++)
#pragma unroll
        for (int j = 0; j < 4; j++)
#pragma unroll
            for (int q = 0; q < 4; q++) acc[i][j][q] = 0.f;

    int amr[4], aq[4];
#pragma unroll
    for (int j = 0; j < 4; ++j) {
        int idx = tid + j * 256;
        amr[j] = idx >> 3;
        aq[j]  = idx & 7;
    }

    auto issueLoads = [&](int c, int s) {
        const int k0 = c * 64;
#pragma unroll
        for (int j = 0; j < 4; ++j) {
            const int m = amr[j], q = aq[j];
            cp_async16(sbB + (uint32_t)s * TILE_BYTES + (uint32_t)m * TROWB + (uint32_t)q * 16,
                       Bt + (size_t)m * K + k0 + q * 8);
            cp_async16(sbA + (uint32_t)s * TILE_BYTES + (uint32_t)m * TROWB + (uint32_t)q * 16,
                       Ah + (size_t)(rowBlk + m) * K + k0 + q * 8);
        }
    };

    const int laneRow  = lane & 15;
    const int laneColB = (lane >> 4) * 16;
    const uint32_t aFragBase = sbA + (uint32_t)(wm + laneRow) * TROWB + laneColB;
    const uint32_t bFragBase = sbB + (uint32_t)(wn + laneRow) * TROWB + laneColB;

    auto compute = [&](int s) {
        const uint32_t aB = aFragBase + (uint32_t)s * TILE_BYTES;
        const uint32_t bB = bFragBase + (uint32_t)s * TILE_BYTES;
#pragma unroll
        for (int ks = 0; ks < 4; ++ks) {
            const uint32_t ko = (uint32_t)ks * 32;
            uint32_t a[4][4], bb[2][4];
#pragma unroll
            for (int mt = 0; mt < 4; ++mt) ldsm_x4(a[mt], aB + (uint32_t)mt * 2304 + ko);
#pragma unroll
            for (int n2 = 0; n2 < 2; ++n2)  ldsm_x4(bb[n2], bB + (uint32_t)n2 * 2304 + ko);
#pragma unroll
            for (int mt = 0; mt < 4; ++mt)
#pragma unroll
                for (int nt = 0; nt < 4; ++nt)
                    mma16816(acc[mt][nt], a[mt][0], a[mt][1], a[mt][2], a[mt][3],
                             bb[nt >> 1][nt & 1], bb[nt >> 1][2 + (nt & 1)]);
        }
    };

    const int nch = K >> 6;   // 8
    issueLoads(0, 0); CP_COMMIT();
    issueLoads(1, 1); CP_COMMIT();
    CP_WAIT1();
    __syncthreads();
    for (int c = 0; c < nch; ++c) {
        const int s = c % 3;
        if (c + 2 < nch) issueLoads(c + 2, (c + 2) % 3);
        CP_COMMIT();
        compute(s);
        CP_WAIT1();
        __syncthreads();
    }

    float* stageL = reinterpret_cast<float*>(smem);    // [128][132]
#pragma unroll
    for (int mt = 0; mt < 4; ++mt) {
#pragma unroll
        for (int nt = 0; nt < 4; ++nt) {
            const int col = wn + nt * 8 + 2 * tg;
            const int r0  = wm + mt * 16 + g;
            *reinterpret_cast<float2*>(&stageL[r0 * 132 + col]) =
                make_float2(acc[mt][nt][0], acc[mt][nt][1]);
            *reinterpret_cast<float2*>(&stageL[(r0 + 8) * 132 + col]) =
                make_float2(acc[mt][nt][2], acc[mt][nt][3]);
        }
    }
    __syncthreads();

    const float inv_t = 1.0f / temp[0];
    float flp = 0.f, fln = 0.f;
    int pc = 0, nc = 0;
#pragma unroll 1
    for (int i = 0; i < 16; ++i) {
        const int r = wid * 16 + i;
        const int* lab = labels + (size_t)(rowBlk + r) * NLAB;
        const int l0 = lab[0];
        float fp = 0.f, fn = 0.f;
        bool any = false;
        for (int c = lane; c < NB; c += 32) {
            const int t = lab[1 + c];
            const float x = stageL[r * 132 + c] * inv_t;
            fp += focal_loss(x, (float)t);
            fn += focal_loss(x, 0.f);
            any |= (t > 0);
        }
#pragma unroll
        for (int o = 16; o > 0; o >>= 1) {
            fp += __shfl_xor_sync(0xffffffffu, fp, o);
            fn += __shfl_xor_sync(0xffffffffu, fn, o);
        }
        const bool pos = __any_sync(0xffffffffu, any);
        const bool neg = (l0 > 0);
        if (lane == 0) {
            if (pos) { flp += fp; pc++; }
            if (neg) { fln += fn; nc++; }
        }
    }
    if (lane == 0) { wredP[wid] = flp; wredN[wid] = fln; wpc[wid] = pc; wnc[wid] = nc; }
    __syncthreads();
    if (tid == 0) {
        float sp = 0.f, sn = 0.f; int cp = 0, cn = 0;
#pragma unroll
        for (int w = 0; w < 8; ++w) { sp += wredP[w]; sn += wredN[w]; cp += wpc[w]; cn += wnc[w]; }
        atomicAdd(&g_acc[0], (double)sp);
        atomicAdd(&g_acc[1], (double)sn);
        if (cp) atomicAdd(&g_cnt[0], (unsigned)cp);
        if (cn) atomicAdd(&g_cnt[1], (unsigned)cn);
    }
}

// ---------------- normalize + distil: warp per row (fp16 sp) ----------------
__global__ void __launch_bounds__(128)
normalize_kernel(const float* __restrict__ traj,
                 const int* __restrict__ sids,
                 const int* __restrict__ oids)
{
    const int tid  = threadIdx.x;
    const int wrp  = tid >> 5;
    const int lane = tid & 31;
    const int r    = blockIdx.x * 4 + wrp;
    __shared__ float dsh[4];

    const int b = r / PPB;
    const int p = r - b * PPB;

    float sp[16], re[16];
    {
        const uint4* spv = reinterpret_cast<const uint4*>(g_sph + (size_t)r * 512) + lane * 2;
        const uint4* rev = reinterpret_cast<const uint4*>(g_reh + (size_t)r * 512) + lane * 2;
#pragma unroll
        for (int i = 0; i < 2; ++i) {
            uint4 u = spv[i];
            const __half2* h = reinterpret_cast<const __half2*>(&u);
#pragma unroll
            for (int j = 0; j < 4; ++j) {
                float2 f = __half22float2(h[j]);
                sp[i * 8 + j * 2]     = f.x;
                sp[i * 8 + j * 2 + 1] = f.y;
            }
        }
#pragma unroll
        for (int i = 0; i < 2; ++i) {
            uint4 u = rev[i];
            const __half2* h = reinterpret_cast<const __half2*>(&u);
#pragma unroll
            for (int j = 0; j < 4; ++j) {
                float2 f = __half22float2(h[j]);
                re[i * 8 + j * 2]     = f.x;
                re[i * 8 + j * 2 + 1] = f.y;
            }
        }
    }
    float ssp = 0.f, sre = 0.f;
#pragma unroll
    for (int i = 0; i < 16; ++i) { ssp += sp[i] * sp[i]; sre += re[i] * re[i]; }
#pragma unroll
    for (int o = 16; o > 0; o >>= 1) {
        ssp += __shfl_xor_sync(0xffffffffu, ssp, o);
        sre += __shfl_xor_sync(0xffffffffu, sre, o);
    }
    const float inv_sp = 1.f / fmaxf(sqrtf(ssp), 1e-12f);
    const float inv_re = 1.f / fmaxf(sqrtf(sre), 1e-12f);

    float comb[16];
    float ssc = 0.f;
#pragma unroll
    for (int i = 0; i < 16; ++i) {
        comb[i] = sp[i] * inv_sp + re[i] * inv_re;
        ssc += comb[i] * comb[i];
    }
#pragma unroll
    for (int o = 16; o > 0; o >>= 1) ssc += __shfl_xor_sync(0xffffffffu, ssc, o);
    const float inv_c = 1.f / fmaxf(sqrtf(ssc), 1e-12f);

    {
        uint4 u[2];
        uint32_t* w = reinterpret_cast<uint32_t*>(u);
#pragma unroll
        for (int j = 0; j < 8; ++j)
            w[j] = f2h2(comb[j * 2] * inv_c, comb[j * 2 + 1] * inv_c);
        uint4* dst = reinterpret_cast<uint4*>(g_combh + (size_t)r * 512) + lane * 2;
        dst[0] = u[0]; dst[1] = u[1];
    }

    const float* tr = (lane < 16)
        ? traj + ((size_t)b * NDET + sids[p]) * 256 + lane * 16
        : traj + ((size_t)b * NDET + oids[p]) * 256 + (lane - 16) * 16;
    float d = 0.f;
#pragma unroll
    for (int i = 0; i < 16; ++i) d += fabsf(tr[i] - sp[i]);
#pragma unroll
    for (int o = 16; o > 0; o >>= 1) d += __shfl_xor_sync(0xffffffffu, d, o);
    if (lane == 0) dsh[wrp] = d;
    __syncthreads();
    if (tid == 0)
        atomicAdd(&g_acc[2], (double)(dsh[0] + dsh[1] + dsh[2] + dsh[3]));
}

// ---------------- finalize ----------------
__global__ void finalize_kernel(float* __restrict__ out) {
    double pc = (double)(g_cnt[0] > 0u ? g_cnt[0] : 1u);
    double nc = (double)(g_cnt[1] > 0u ? g_cnt[1] : 1u);
    double total = g_acc[0] / (pc * (double)NB)
                 + g_acc[1] / (nc * (double)NB)
                 + g_acc[2] / ((double)MROWS * 512.0);
    out[0] = (float)total;
}

// ---------------- launch ----------------
extern "C" void kernel_launch(void* const* d_in, const int* in_sizes, int n_in,
                              void* d_out, int out_size)
{
    const float* det    = (const float*)d_in[0];
    const float* traj   = (const float*)d_in[1];
    const float* rp     = (const float*)d_in[2];
    const float* cw     = (const float*)d_in[3];
    const float* W1     = (const float*)d_in[4];
    const float* b1     = (const float*)d_in[5];
    const float* W2     = (const float*)d_in[6];
    const float* b2     = (const float*)d_in[7];
    const float* W3     = (const float*)d_in[8];
    const float* R1     = (const float*)d_in[9];
    const float* rb1    = (const float*)d_in[10];
    const float* R2     = (const float*)d_in[11];
    const float* temp   = (const float*)d_in[12];
    const int*   labels = (const int*)d_in[13];
    const int*   sids   = (const int*)d_in[14];
    const int*   oids   = (const int*)d_in[15];
    float* out = (float*)d_out;

    void *p_deth, *p_uvh, *p_h2h, *p_sph, *p_reh, *p_combh,
         *p_w1t, *p_w2t, *p_w3t, *p_r2t, *p_cwp;
    cudaGetSymbolAddress(&p_deth, g_deth);
    cudaGetSymbolAddress(&p_uvh, g_UVh);
    cudaGetSymbolAddress(&p_h2h, g_h2h);
    cudaGetSymbolAddress(&p_sph, g_sph);
    cudaGetSymbolAddress(&p_reh, g_reh);
    cudaGetSymbolAddress(&p_combh, g_combh);
    cudaGetSymbolAddress(&p_w1t, g_W1t);
    cudaGetSymbolAddress(&p_w2t, g_W2t);
    cudaGetSymbolAddress(&p_w3t, g_W3t);
    cudaGetSymbolAddress(&p_r2t, g_R2t);
    cudaGetSymbolAddress(&p_cwp, g_cwp);
    __half* DETH  = (__half*)p_deth;
    __half* UVH   = (__half*)p_uvh;
    __half* H2H   = (__half*)p_h2h;
    __half* SPH   = (__half*)p_sph;
    __half* REH   = (__half*)p_reh;
    __half* COMBH = (__half*)p_combh;
    __half* W1T   = (__half*)p_w1t;
    __half* W2T   = (__half*)p_w2t;
    __half* W3T   = (__half*)p_w3t;
    __half* R2T   = (__half*)p_r2t;

    cudaFuncSetAttribute(mma_gemmW<1>, cudaFuncAttributeMaxDynamicSharedMemorySize, GEMM_SMEMW);
    cudaFuncSetAttribute(mma_gemmW<2>, cudaFuncAttributeMaxDynamicSharedMemorySize, GEMM_SMEMW);
    cudaFuncSetAttribute(mma_gemmW<4>, cudaFuncAttributeMaxDynamicSharedMemorySize, GEMM_SMEMW);
    cudaFuncSetAttribute(mma_logits, cudaFuncAttributeMaxDynamicSharedMemorySize, GEMM_SMEM);

    // ALL prep in one launch
    prep_kernel<<<PREP_BLOCKS, 256>>>(det, W1, W2, W3, R2, cw);

    // UV' = det @ [W1U | W1V]  (fp16, +b1 on U half)
    mma_gemmW<4><<<dim3(8, 6), 512, GEMM_SMEMW>>>(2048, DETH, 2048, W1T, UVH, 2048,
                                                  b1, nullptr, nullptr, nullptr);
    // h2 = relu(relu(U'_s + V_o) @ W2 + b2)  (fp16)
    mma_gemmW<1><<<dim3(4, MROWS / 128), 512, GEMM_SMEMW>>>(1024, nullptr, 0, W2T, H2H, 1024,
                                                            nullptr, b2, sids, oids);
    // so_proj = h2 @ W3   (fp16, no bias)
    mma_gemmW<4><<<dim3(2, MROWS / 128), 512, GEMM_SMEMW>>>(1024, H2H, 1024, W3T, SPH, 512,
                                                            nullptr, nullptr, nullptr, nullptr);
    // re = relu(rp @ R1 + rb1) @ R2   (fp16)
    mma_gemmW<2><<<dim3(2, MROWS / 128), 512, GEMM_SMEMW>>>(256, rp, 12, R2T, REH, 512,
                                                            R1, rb1, nullptr, nullptr);
    // normalize + distil
    normalize_kernel<<<MROWS / 4, 128>>>(traj, sids, oids);
    // logits + fused focal
    mma_logits<<<dim3(1, MROWS / 128), 256, GEMM_SMEM>>>(COMBH, (__half*)p_cwp, labels, temp);
    finalize_kernel<<<1, 1>>>(out);
}